// round 16
// baseline (speedup 1.0000x reference)
#include <cuda_runtime.h>

// ---------------------------------------------------------------------------
// MultitaskSNN round 16: QUARTER-NEURON SPLIT, BATCH-PACKED f32x2.
// 4 threads per batch pair (65536 threads -> 14 warps/SM, 2 CTAs x 224).
// f32x2 lanes = {batchA, batchB}: spike/x u64s multiply weight {w,w} pairs
// DIRECTLY (no dup-packing in inner loops - R4's killer). Thread h owns
// L1 neurons 7h..7h+6, 7 padded branch outputs, 1 out neuron. Spikes move
// between the 4 threads via width-4 SHFL on demand (1 per input, minimal
// register liveness). Compare-LIF; ascending-i chains; bias after sum
// -> bit-exact vs reference (rel_err 0.0 expected).
// ---------------------------------------------------------------------------

typedef unsigned long long u64;
typedef unsigned int u32;

#define TT 50
#define NIN 32
#define THREADS 224

// u64-unit smem offsets
#define UW1  0      // [i=32][32]: slot 8h+n = {Wsh[7h+n][i]}x2
#define UB1  1024   // [32]
#define UW24 1056   // [i=28][32]: slot 8h+n = branch weight {w,w}
#define UB24 1952   // [32]
#define UW5  1984   // [j=14][4]: out weights {w,w} per h
#define UB5  2040   // [4]
#define SW_U64 2044

__device__ __forceinline__ u64 pack2(float lo, float hi) {
    u64 r; asm("mov.b64 %0, {%1, %2};" : "=l"(r) : "f"(lo), "f"(hi)); return r;
}
__device__ __forceinline__ void unpack2(u64 v, float& lo, float& hi) {
    asm("mov.b64 {%0, %1}, %2;" : "=f"(lo), "=f"(hi) : "l"(v));
}
__device__ __forceinline__ u64 fma2(u64 a, u64 b, u64 c) {
    u64 d; asm("fma.rn.f32x2 %0, %1, %2, %3;" : "=l"(d) : "l"(a), "l"(b), "l"(c)); return d;
}
__device__ __forceinline__ u64 add2(u64 a, u64 b) {
    u64 d; asm("add.rn.f32x2 %0, %1, %2;" : "=l"(d) : "l"(a), "l"(b)); return d;
}

#define BETA2 0x3F6666663F666666ull  // {0.9f, 0.9f}

// compare-LIF with spike output (bit-exact proven):
//   r=(m>1)?-1:0;  m=add(fma(beta,m,cur),r);  spike=(m_new>1)
__device__ __forceinline__ u64 lifx(u64& m2, u64 cur2) {
    float m0, m1;
    unpack2(m2, m0, m1);
    float r0 = (m0 > 1.0f) ? -1.0f : 0.0f;
    float r1 = (m1 > 1.0f) ? -1.0f : 0.0f;
    m2 = add2(fma2(BETA2, m2, cur2), pack2(r0, r1));
    float n0, n1;
    unpack2(m2, n0, n1);
    return pack2((n0 > 1.0f) ? 1.0f : 0.0f, (n1 > 1.0f) ? 1.0f : 0.0f);
}
__device__ __forceinline__ void lif2c(u64& m2, u64 cur2) {
    float m0, m1;
    unpack2(m2, m0, m1);
    float r0 = (m0 > 1.0f) ? -1.0f : 0.0f;
    float r1 = (m1 > 1.0f) ? -1.0f : 0.0f;
    m2 = add2(fma2(BETA2, m2, cur2), pack2(r0, r1));
}

__device__ __forceinline__ u64 shfl4(u64 v, int src) {
    return __shfl_sync(0xffffffffu, v, src, 4);
}

__global__ __launch_bounds__(THREADS, 2) void snn_kernel(
    const float* __restrict__ x,
    const float* __restrict__ Wsh, const float* __restrict__ bsh,
    const float* __restrict__ Wch, const float* __restrict__ bch,
    const float* __restrict__ Wco, const float* __restrict__ bco,
    const float* __restrict__ Wrh, const float* __restrict__ brh,
    const float* __restrict__ Wro, const float* __restrict__ bro,
    float* __restrict__ out, int B)
{
    __shared__ __align__(16) u64 swu[SW_U64];
    float* swf = (float*)swu;
    const int tid = threadIdx.x;

    for (int i = tid; i < SW_U64; i += THREADS) swu[i] = 0ull;
    __syncthreads();

    // L1: slot 8h+n holds {Wsh[q][i]}x2, q = 7h+n
    for (int idx = tid; idx < 32 * 28; idx += THREADS) {
        int i = idx / 28, q = idx % 28;
        float w = Wsh[q * NIN + i];
        swu[UW1 + i * 32 + 8 * (q / 7) + (q % 7)] = pack2(w, w);
    }
    for (int q = tid; q < 28; q += THREADS)
        swu[UB1 + 8 * (q / 7) + (q % 7)] = pack2(bsh[q], bsh[q]);
    // branch: 22 real outputs mapped to (h, n)
    for (int idx = tid; idx < 22 * 28; idx += THREADS) {
        int o = idx / 28, i = idx % 28;
        int hh, nn;
        if (o < 7)       { hh = 0; nn = o; }
        else if (o == 7) { hh = 1; nn = 0; }
        else {
            int r = o - 8;
            if (r < 6)       { hh = 1; nn = r + 1; }
            else if (r < 13) { hh = 2; nn = r - 6; }
            else             { hh = 3; nn = 0; }
        }
        float w = (o < 8) ? Wch[o * 28 + i] : Wrh[(o - 8) * 28 + i];
        swu[UW24 + i * 32 + 8 * hh + nn] = pack2(w, w);
    }
    for (int o = tid; o < 22; o += THREADS) {
        int hh, nn;
        if (o < 7)       { hh = 0; nn = o; }
        else if (o == 7) { hh = 1; nn = 0; }
        else {
            int r = o - 8;
            if (r < 6)       { hh = 1; nn = r + 1; }
            else if (r < 13) { hh = 2; nn = r - 6; }
            else             { hh = 3; nn = 0; }
        }
        float b = (o < 8) ? bch[o] : brh[o - 8];
        swu[UB24 + 8 * hh + nn] = pack2(b, b);
    }
    // out: [j][h]
    for (int idx = tid; idx < 14 * 4; idx += THREADS) {
        int j = idx / 4, hh = idx % 4;
        float w = 0.0f;
        if (hh < 3) { if (j < 8) w = Wco[hh * 8 + j]; }
        else        w = Wro[j];
        swu[UW5 + j * 4 + hh] = pack2(w, w);
    }
    if (tid < 4) {
        float b = (tid < 3) ? bco[tid] : bro[0];
        swu[UB5 + tid] = pack2(b, b);
    }
    __syncthreads();

    const int g   = blockIdx.x * THREADS + tid;
    const int grp = g >> 2;
    if (grp >= B / 2) return;          // warp-uniform (boundary % 32 == 0)
    const int h  = g & 3;
    const int bA = 2 * grp;

    const u64* w1  = swu + UW1  + 8 * h;   // + i*32
    const u64* b1  = swu + UB1  + 8 * h;
    const u64* w24 = swu + UW24 + 8 * h;
    const u64* b24 = swu + UB24 + 8 * h;

    // batch-packed membranes {A, B}
    u64 ms[7], mb[7], mo = 0ull;
#pragma unroll
    for (int n = 0; n < 7; n++) { ms[n] = 0ull; mb[n] = 0ull; }

    const size_t TB = (size_t)TT * B;
    float* p_mco = out;                 // [T,B,3]
    float* p_sch = out + TB * 3;        // [T,B,8]
    float* p_mro = out + TB * 11;       // [T,B,1]
    float* p_srh = out + TB * 12;       // [T,B,14]
    float* p_ssh = out + TB * 26;       // [T,B,28]

    const size_t xstep = (size_t)B * NIN;
    const float* xbase = x + (size_t)bA * NIN;

#pragma unroll 1
    for (int t = 0; t < TT; t++) {
        const float* xp = xbase + (size_t)t * xstep;
        if (t + 1 < TT && h == 0) {
            asm volatile("prefetch.global.L2 [%0];" :: "l"(xp + xstep));
            asm volatile("prefetch.global.L2 [%0];" :: "l"(xp + xstep + NIN));
        }

        // ---- Layer 1: 7 own neurons x 2 batches <- 32 inputs ----
        u64 acc[7];
#pragma unroll
        for (int n = 0; n < 7; n++) acc[n] = 0ull;
#pragma unroll
        for (int k = 0; k < 4; k++) {       // chunks of 8 inputs
            float4 aL = __ldcs((const float4*)xp + 2 * k);
            float4 aH = __ldcs((const float4*)xp + 2 * k + 1);
            float4 bL = __ldcs((const float4*)(xp + NIN) + 2 * k);
            float4 bH = __ldcs((const float4*)(xp + NIN) + 2 * k + 1);
            u64 xv[8];
            xv[0] = pack2(aL.x, bL.x); xv[1] = pack2(aL.y, bL.y);
            xv[2] = pack2(aL.z, bL.z); xv[3] = pack2(aL.w, bL.w);
            xv[4] = pack2(aH.x, bH.x); xv[5] = pack2(aH.y, bH.y);
            xv[6] = pack2(aH.z, bH.z); xv[7] = pack2(aH.w, bH.w);
#pragma unroll
            for (int j = 0; j < 8; j++) {
                const u64* w = w1 + (8 * k + j) * 32;
                ulonglong2 w01 = *(const ulonglong2*)(w);
                ulonglong2 w23 = *(const ulonglong2*)(w + 2);
                ulonglong2 w45 = *(const ulonglong2*)(w + 4);
                u64 w6 = w[6];
                acc[0] = fma2(xv[j], w01.x, acc[0]);
                acc[1] = fma2(xv[j], w01.y, acc[1]);
                acc[2] = fma2(xv[j], w23.x, acc[2]);
                acc[3] = fma2(xv[j], w23.y, acc[3]);
                acc[4] = fma2(xv[j], w45.x, acc[4]);
                acc[5] = fma2(xv[j], w45.y, acc[5]);
                acc[6] = fma2(xv[j], w6,    acc[6]);
            }
        }

        // ---- L1 LIF + store own spk_sh (neurons 7h..7h+6) ----
        u64 ss[7];
        {
            float* pA = p_ssh + ((size_t)t * B + bA) * 28 + 7 * h;
            float* pB = pA + 28;
#pragma unroll
            for (int n = 0; n < 7; n++) {
                ss[n] = lifx(ms[n], add2(acc[n], b1[n]));
                float a, b;
                unpack2(ss[n], a, b);
                __stcs(pA + n, a);
                __stcs(pB + n, b);
            }
        }

        // ---- branch layer: 7 padded outputs <- 28 spikes (shfl on demand) ----
        u64 cc[7];
#pragma unroll
        for (int n = 0; n < 7; n++) cc[n] = 0ull;
#pragma unroll
        for (int i = 0; i < 28; i++) {
            u64 sp = shfl4(ss[i % 7], i / 7);   // batch-packed spike i
            const u64* w = w24 + i * 32;
            ulonglong2 w01 = *(const ulonglong2*)(w);
            ulonglong2 w23 = *(const ulonglong2*)(w + 2);
            ulonglong2 w45 = *(const ulonglong2*)(w + 4);
            u64 w6 = w[6];
            cc[0] = fma2(sp, w01.x, cc[0]);
            cc[1] = fma2(sp, w01.y, cc[1]);
            cc[2] = fma2(sp, w23.x, cc[2]);
            cc[3] = fma2(sp, w23.y, cc[3]);
            cc[4] = fma2(sp, w45.x, cc[4]);
            cc[5] = fma2(sp, w45.y, cc[5]);
            cc[6] = fma2(sp, w6,    cc[6]);
        }
        u64 sb[7];
#pragma unroll
        for (int n = 0; n < 7; n++)
            sb[n] = lifx(mb[n], add2(cc[n], b24[n]));

        // ---- store branch spikes (per-h targets) ----
        {
            const size_t row = (size_t)t * B + bA;
            if (h == 0) {
                float* p = p_sch + row * 8;
#pragma unroll
                for (int n = 0; n < 7; n++) {
                    float a, b;
                    unpack2(sb[n], a, b);
                    __stcs(p + n, a);
                    __stcs(p + 8 + n, b);
                }
            } else if (h == 1) {
                float a, b;
                unpack2(sb[0], a, b);
                float* pc = p_sch + row * 8;
                __stcs(pc + 7, a);
                __stcs(pc + 15, b);
                float* pr = p_srh + row * 14;
#pragma unroll
                for (int n = 1; n < 7; n++) {
                    unpack2(sb[n], a, b);
                    __stcs(pr + (n - 1), a);
                    __stcs(pr + 14 + (n - 1), b);
                }
            } else if (h == 2) {
                float* pr = p_srh + row * 14;
#pragma unroll
                for (int n = 0; n < 7; n++) {
                    float a, b;
                    unpack2(sb[n], a, b);
                    __stcs(pr + 6 + n, a);
                    __stcs(pr + 20 + n, b);
                }
            } else {
                float a, b;
                unpack2(sb[0], a, b);
                float* pr = p_srh + row * 14;
                __stcs(pr + 13, a);
                __stcs(pr + 27, b);
            }
        }

        // ---- out layer: thread h computes out neuron h ----
        // h<3: class out h <- ch[0..7];  h==3: reg out <- rh[0..13]
        u64 oo = 0ull;
#pragma unroll
        for (int j = 0; j < 14; j++) {
            // class input ch_j (valid j<8): owner/value pure functions of j
            const int c_src = (j < 7) ? 0 : 1;
            const int c_n   = (j < 7) ? j : 0;
            // reg input rh_j: owner/value pure functions of j
            const int r_src = (j < 6) ? 1 : ((j < 13) ? 2 : 3);
            const int r_n   = (j < 6) ? j + 1 : ((j < 13) ? j - 6 : 0);
            u64 v1 = shfl4(sb[c_n], c_src);
            u64 v2 = shfl4(sb[r_n], r_src);
            u64 v  = (h == 3) ? v2 : v1;
            oo = fma2(v, swu[UW5 + j * 4 + h], oo);   // zero weight for class j>=8
        }
        lif2c(mo, add2(oo, swu[UB5 + h]));

        {
            const size_t row = (size_t)t * B + bA;
            float a, b;
            unpack2(mo, a, b);
            if (h < 3) {
                float* p = p_mco + row * 3;
                __stcs(p + h, a);
                __stcs(p + 3 + h, b);
            } else {
                __stcs(p_mro + row, a);
                __stcs(p_mro + row + 1, b);
            }
        }
    }
}

extern "C" void kernel_launch(void* const* d_in, const int* in_sizes, int n_in,
                              void* d_out, int out_size) {
    const float* x   = (const float*)d_in[0];
    const float* Wsh = (const float*)d_in[1];
    const float* bsh = (const float*)d_in[2];
    const float* Wch = (const float*)d_in[3];
    const float* bch = (const float*)d_in[4];
    const float* Wco = (const float*)d_in[5];
    const float* bco = (const float*)d_in[6];
    const float* Wrh = (const float*)d_in[7];
    const float* brh = (const float*)d_in[8];
    const float* Wro = (const float*)d_in[9];
    const float* bro = (const float*)d_in[10];

    const int B = in_sizes[0] / (TT * NIN);
    const int total = 2 * B;                       // 4 threads per batch pair
    const int blocks = (total + THREADS - 1) / THREADS;

    snn_kernel<<<blocks, THREADS>>>(x, Wsh, bsh, Wch, bch, Wco, bco,
                                    Wrh, brh, Wro, bro, (float*)d_out, B);
}

// round 17
// speedup vs baseline: 4.0310x; 4.0310x over previous
#include <cuda_runtime.h>

// ---------------------------------------------------------------------------
// MultitaskSNN round 17: R10 compute core + WARP-PRIVATE SMEM I/O STAGING.
// R10's wavefront audit: weights ~320, x LDG ~256 (128B-strided lanes),
// stores ~300 (56B-strided STG.64) per warp-step. This round:
//  - warp cooperatively loads its 32 contiguous batch rows of x (4KB) with
//    8 coalesced LDG.128 into a warp-private SMEM tile (36-float row pad);
//  - outputs are staged into the same tile (reused after x is consumed) and
//    flushed with coalesced STG.128 over contiguous 32-row global spans.
// Synchronization is __syncwarp ONLY (no block barriers - R15's killer).
// Compute arithmetic byte-identical to R10 -> bit-exact (rel_err 0.0).
// ---------------------------------------------------------------------------

typedef unsigned long long u64;
typedef unsigned int u32;

#define TT 50
#define NIN 32
#define THREADS 224
#define NWARP 7

// weight smem (u64 units), same layout as R10
#define UW1  0      // [i=32][slot=16]
#define UB1  512
#define UW24 528    // [i=28][slot=16]
#define UB24 976
#define UW5  992    // [i=14][slot=4]
#define UB5  1048
#define SW_U64 1052

// warp-private stage: 1792 floats per warp
//  phase X: 32 rows x 36 floats (padded) = 1152
//  phase O: SH 0..896 | SCH 896..1152 | SRH 1152..1600 | MCO 1600..1696 | MRO 1696..1728
#define STG_F   1792
#define OSH  0
#define OSCH 896
#define OSRH 1152
#define OMCO 1600
#define OMRO 1696

#define SMEM_BYTES (SW_U64 * 8 + NWARP * STG_F * 4)   // 8416 + 50176 = 58592

__device__ __forceinline__ u64 pack2(float lo, float hi) {
    u64 r; asm("mov.b64 %0, {%1, %2};" : "=l"(r) : "f"(lo), "f"(hi)); return r;
}
__device__ __forceinline__ void unpack2(u64 v, float& lo, float& hi) {
    asm("mov.b64 {%0, %1}, %2;" : "=f"(lo), "=f"(hi) : "l"(v));
}
__device__ __forceinline__ u64 fma2(u64 a, u64 b, u64 c) {
    u64 d; asm("fma.rn.f32x2 %0, %1, %2, %3;" : "=l"(d) : "l"(a), "l"(b), "l"(c)); return d;
}
__device__ __forceinline__ u64 add2(u64 a, u64 b) {
    u64 d; asm("add.rn.f32x2 %0, %1, %2;" : "=l"(d) : "l"(a), "l"(b)); return d;
}

#define BETA2 0x3F6666663F666666ull  // {0.9f, 0.9f}

// compare-LIF with spike output (bit-exact proven)
__device__ __forceinline__ u64 lifx(u64& m2, u64 cur2) {
    float m0, m1;
    unpack2(m2, m0, m1);
    float r0 = (m0 > 1.0f) ? -1.0f : 0.0f;
    float r1 = (m1 > 1.0f) ? -1.0f : 0.0f;
    m2 = add2(fma2(BETA2, m2, cur2), pack2(r0, r1));
    float n0, n1;
    unpack2(m2, n0, n1);
    return pack2((n0 > 1.0f) ? 1.0f : 0.0f, (n1 > 1.0f) ? 1.0f : 0.0f);
}
__device__ __forceinline__ void lif2c(u64& m2, u64 cur2) {
    float m0, m1;
    unpack2(m2, m0, m1);
    float r0 = (m0 > 1.0f) ? -1.0f : 0.0f;
    float r1 = (m1 > 1.0f) ? -1.0f : 0.0f;
    m2 = add2(fma2(BETA2, m2, cur2), pack2(r0, r1));
}

__global__ __launch_bounds__(THREADS, 1) void snn_kernel(
    const float* __restrict__ x,
    const float* __restrict__ Wsh, const float* __restrict__ bsh,
    const float* __restrict__ Wch, const float* __restrict__ bch,
    const float* __restrict__ Wco, const float* __restrict__ bco,
    const float* __restrict__ Wrh, const float* __restrict__ brh,
    const float* __restrict__ Wro, const float* __restrict__ bro,
    float* __restrict__ out, int B)
{
    extern __shared__ __align__(16) u64 dsm[];
    u64*   swu = dsm;
    float* swf = (float*)dsm;
    float* stage_all = (float*)(dsm + SW_U64);
    const int tid = threadIdx.x;

    for (int i = tid; i < SW_U64; i += THREADS) swu[i] = 0ull;
    __syncthreads();

    // weights (R10 layout)
    for (int idx = tid; idx < 32 * 14; idx += THREADS) {
        int i = idx / 14, p = idx % 14, hh = p / 7, pp = p % 7;
        int o = 14 * hh + 2 * pp;
        int u = UW1 + i * 16 + 8 * hh + pp;
        swf[2 * u + 0] = Wsh[o * NIN + i];
        swf[2 * u + 1] = Wsh[(o + 1) * NIN + i];
    }
    for (int p = tid; p < 14; p += THREADS) {
        int hh = p / 7, pp = p % 7, o = 14 * hh + 2 * pp;
        swf[2 * (UB1 + 8 * hh + pp) + 0] = bsh[o];
        swf[2 * (UB1 + 8 * hh + pp) + 1] = bsh[o + 1];
    }
    for (int idx = tid; idx < 8 * 28; idx += THREADS) {
        int o = idx / 28, i = idx % 28;
        swf[2 * (UW24 + i * 16 + (o >> 1)) + (o & 1)] = Wch[idx];
    }
    for (int idx = tid; idx < 14 * 28; idx += THREADS) {
        int o = idx / 28, i = idx % 28;
        swf[2 * (UW24 + i * 16 + 8 + (o >> 1)) + (o & 1)] = Wrh[idx];
    }
    for (int o = tid; o < 8; o += THREADS)
        swf[2 * (UB24 + (o >> 1)) + (o & 1)] = bch[o];
    for (int o = tid; o < 14; o += THREADS)
        swf[2 * (UB24 + 8 + (o >> 1)) + (o & 1)] = brh[o];
    for (int i = tid; i < 8; i += THREADS) {
        swf[2 * (UW5 + i * 4 + 0) + 0] = Wco[0 * 8 + i];
        swf[2 * (UW5 + i * 4 + 0) + 1] = Wco[1 * 8 + i];
        swf[2 * (UW5 + i * 4 + 1) + 0] = Wco[2 * 8 + i];
    }
    for (int i = tid; i < 14; i += THREADS)
        swf[2 * (UW5 + i * 4 + 2) + 0] = Wro[i];
    if (tid == 0) {
        swf[2 * (UB5 + 0) + 0] = bco[0];
        swf[2 * (UB5 + 0) + 1] = bco[1];
        swf[2 * (UB5 + 1) + 0] = bco[2];
        swf[2 * (UB5 + 2) + 0] = bro[0];
    }
    __syncthreads();

    const int warp = tid >> 5;
    const int lane = tid & 31;
    const int wb   = blockIdx.x * THREADS + warp * 32;   // warp's batch base
    if (wb >= B) return;                                  // whole warp exits

    float* stg = stage_all + warp * STG_F;   // warp-private stage

    const int h  = lane & 1;
    const int rA = lane & ~1;            // local row of batch A (0..30 even)
    const int bA = wb + rA;              // global batch pair base

    const u64* w1  = swu + UW1  + 8 * h;
    const u64* b1  = swu + UB1  + 8 * h;
    const u64* w24 = swu + UW24 + 8 * h;
    const u64* b24 = swu + UB24 + 8 * h;
    const u64* w5  = swu + UW5  + 2 * h;
    const u64* b5  = swu + UB5  + 2 * h;

    u64 msA[7], msB[7], mbA[7], mbB[7];
    u64 moA0 = 0ull, moA1 = 0ull, moB0 = 0ull, moB1 = 0ull;
#pragma unroll
    for (int p = 0; p < 7; p++) {
        msA[p] = 0ull; msB[p] = 0ull; mbA[p] = 0ull; mbB[p] = 0ull;
    }

    const size_t TB = (size_t)TT * B;
    float* p_mco = out;                 // [T,B,3]
    float* p_sch = out + TB * 3;        // [T,B,8]
    float* p_mro = out + TB * 11;       // [T,B,1]
    float* p_srh = out + TB * 12;       // [T,B,14]
    float* p_ssh = out + TB * 26;       // [T,B,28]

#pragma unroll 1
    for (int t = 0; t < TT; t++) {
        // ---- warp-cooperative coalesced x load (32 rows = 1024 floats) ----
        {
            const float4* xg4 = (const float4*)(x + ((size_t)t * B + wb) * NIN);
#pragma unroll
            for (int k = 0; k < 8; k++) {
                int idx = lane + 32 * k;          // 0..255
                float4 v = __ldcs(xg4 + idx);
                int row = idx >> 3, col = (idx & 7) * 4;
                *(float4*)(stg + row * 36 + col) = v;
            }
            if (t + 1 < TT)
                asm volatile("prefetch.global.L2 [%0];"
                             :: "l"((const char*)(xg4 + 256) + lane * 128));
        }
        __syncwarp();

        // ---- Layer 1: 7 neuron-pairs x 2 batches <- 32 inputs (smem) ----
        u64 aA[7], aB[7];
#pragma unroll
        for (int p = 0; p < 7; p++) { aA[p] = 0ull; aB[p] = 0ull; }
#pragma unroll
        for (int k = 0; k < 8; k++) {
            float4 a4 = *(const float4*)(stg + rA * 36 + 4 * k);
            float4 b4 = *(const float4*)(stg + (rA + 1) * 36 + 4 * k);
            const float av[4] = {a4.x, a4.y, a4.z, a4.w};
            const float bv[4] = {b4.x, b4.y, b4.z, b4.w};
#pragma unroll
            for (int j = 0; j < 4; j++) {
                u64 dA = pack2(av[j], av[j]);
                u64 dB = pack2(bv[j], bv[j]);
                const u64* w = w1 + (4 * k + j) * 16;
                ulonglong2 w01 = *(const ulonglong2*)(w);
                ulonglong2 w23 = *(const ulonglong2*)(w + 2);
                ulonglong2 w45 = *(const ulonglong2*)(w + 4);
                u64 w6 = w[6];
                aA[0] = fma2(dA, w01.x, aA[0]); aB[0] = fma2(dB, w01.x, aB[0]);
                aA[1] = fma2(dA, w01.y, aA[1]); aB[1] = fma2(dB, w01.y, aB[1]);
                aA[2] = fma2(dA, w23.x, aA[2]); aB[2] = fma2(dB, w23.x, aB[2]);
                aA[3] = fma2(dA, w23.y, aA[3]); aB[3] = fma2(dB, w23.y, aB[3]);
                aA[4] = fma2(dA, w45.x, aA[4]); aB[4] = fma2(dB, w45.x, aB[4]);
                aA[5] = fma2(dA, w45.y, aA[5]); aB[5] = fma2(dB, w45.y, aB[5]);
                aA[6] = fma2(dA, w6,    aA[6]); aB[6] = fma2(dB, w6,    aB[6]);
            }
        }
        __syncwarp();      // all x reads done before stage is overwritten

        // ---- L1 LIF + stage spk_sh ----
        u64 ssA[7], ssB[7];
        {
            float* pA = stg + OSH + rA * 28 + 14 * h;
            float* pB = pA + 28;
#pragma unroll
            for (int p = 0; p < 7; p++) {
                ssA[p] = lifx(msA[p], add2(aA[p], b1[p]));
                ssB[p] = lifx(msB[p], add2(aB[p], b1[p]));
                float a0, a1, b0, b1f;
                unpack2(ssA[p], a0, a1);
                unpack2(ssB[p], b0, b1f);
                ((float2*)pA)[p] = make_float2(a0, a1);
                ((float2*)pB)[p] = make_float2(b0, b1f);
            }
        }

        // ---- exchange spike pairs with partner thread ----
        u64 sAf[14], sBf[14];
#pragma unroll
        for (int p = 0; p < 7; p++) {
            u64 qA = __shfl_xor_sync(0xffffffffu, ssA[p], 1);
            u64 qB = __shfl_xor_sync(0xffffffffu, ssB[p], 1);
            sAf[p]     = h ? qA     : ssA[p];
            sAf[7 + p] = h ? ssA[p] : qA;
            sBf[p]     = h ? qB     : ssB[p];
            sBf[7 + p] = h ? ssB[p] : qB;
        }

        // ---- branch layer: 7 neuron-pairs x 2 batches <- 28 spikes ----
        u64 cA[7], cB[7];
#pragma unroll
        for (int p = 0; p < 7; p++) { cA[p] = 0ull; cB[p] = 0ull; }
#pragma unroll
        for (int pp = 0; pp < 14; pp++) {
            float sa0, sa1, sb0, sb1;
            unpack2(sAf[pp], sa0, sa1);
            unpack2(sBf[pp], sb0, sb1);
#pragma unroll
            for (int half = 0; half < 2; half++) {
                const float sa = half ? sa1 : sa0;
                const float sb = half ? sb1 : sb0;
                const int i = 2 * pp + half;
                u64 dA = pack2(sa, sa);
                u64 dB = pack2(sb, sb);
                const u64* w = w24 + i * 16;
                ulonglong2 w01 = *(const ulonglong2*)(w);
                ulonglong2 w23 = *(const ulonglong2*)(w + 2);
                ulonglong2 w45 = *(const ulonglong2*)(w + 4);
                u64 w6 = w[6];
                cA[0] = fma2(dA, w01.x, cA[0]); cB[0] = fma2(dB, w01.x, cB[0]);
                cA[1] = fma2(dA, w01.y, cA[1]); cB[1] = fma2(dB, w01.y, cB[1]);
                cA[2] = fma2(dA, w23.x, cA[2]); cB[2] = fma2(dB, w23.x, cB[2]);
                cA[3] = fma2(dA, w23.y, cA[3]); cB[3] = fma2(dB, w23.y, cB[3]);
                cA[4] = fma2(dA, w45.x, cA[4]); cB[4] = fma2(dB, w45.x, cB[4]);
                cA[5] = fma2(dA, w45.y, cA[5]); cB[5] = fma2(dB, w45.y, cB[5]);
                cA[6] = fma2(dA, w6,    cA[6]); cB[6] = fma2(dB, w6,    cB[6]);
            }
        }
        u64 sbA[7], sbB[7];
#pragma unroll
        for (int p = 0; p < 7; p++) {
            sbA[p] = lifx(mbA[p], add2(cA[p], b24[p]));
            sbB[p] = lifx(mbB[p], add2(cB[p], b24[p]));
        }

        // ---- stage branch spikes ----
        if (h == 0) {
            float f0, f1, f2, f3, f4, f5, f6, f7;
            float* p = stg + OSCH + rA * 8;
            unpack2(sbA[0], f0, f1); unpack2(sbA[1], f2, f3);
            unpack2(sbA[2], f4, f5); unpack2(sbA[3], f6, f7);
            ((float4*)p)[0] = make_float4(f0, f1, f2, f3);
            ((float4*)p)[1] = make_float4(f4, f5, f6, f7);
            unpack2(sbB[0], f0, f1); unpack2(sbB[1], f2, f3);
            unpack2(sbB[2], f4, f5); unpack2(sbB[3], f6, f7);
            ((float4*)p)[2] = make_float4(f0, f1, f2, f3);
            ((float4*)p)[3] = make_float4(f4, f5, f6, f7);
        } else {
            float* p = stg + OSRH + rA * 14;
#pragma unroll
            for (int k = 0; k < 7; k++) {
                float a0, a1, b0, b1f;
                unpack2(sbA[k], a0, a1);
                unpack2(sbB[k], b0, b1f);
                ((float2*)p)[k]     = make_float2(a0, a1);
                ((float2*)p)[k + 7] = make_float2(b0, b1f);
            }
        }

        // ---- out layer ----
        u64 oA0 = 0ull, oA1 = 0ull, oB0 = 0ull, oB1 = 0ull;
#pragma unroll
        for (int pp = 0; pp < 7; pp++) {
            float sa0, sa1, sb0, sb1;
            unpack2(sbA[pp], sa0, sa1);
            unpack2(sbB[pp], sb0, sb1);
#pragma unroll
            for (int half = 0; half < 2; half++) {
                const float sa = half ? sa1 : sa0;
                const float sb = half ? sb1 : sb0;
                const int i = 2 * pp + half;
                u64 dA = pack2(sa, sa);
                u64 dB = pack2(sb, sb);
                ulonglong2 wp = *(const ulonglong2*)(w5 + i * 4);
                oA0 = fma2(dA, wp.x, oA0); oA1 = fma2(dA, wp.y, oA1);
                oB0 = fma2(dB, wp.x, oB0); oB1 = fma2(dB, wp.y, oB1);
            }
        }
        lif2c(moA0, add2(oA0, b5[0]));
        lif2c(moA1, add2(oA1, b5[1]));
        lif2c(moB0, add2(oB0, b5[0]));
        lif2c(moB1, add2(oB1, b5[1]));

        if (h == 0) {
            float a0, a1, a2, pd, b0, b1f, b2;
            unpack2(moA0, a0, a1); unpack2(moA1, a2, pd);
            unpack2(moB0, b0, b1f); unpack2(moB1, b2, pd);
            float* p = stg + OMCO + rA * 3;
            ((float2*)p)[0] = make_float2(a0, a1);
            ((float2*)p)[1] = make_float2(a2, b0);
            ((float2*)p)[2] = make_float2(b1f, b2);
        } else {
            float rAo, rBo, pd;
            unpack2(moA0, rAo, pd);
            unpack2(moB0, rBo, pd);
            *(float2*)(stg + OMRO + rA) = make_float2(rAo, rBo);
        }
        __syncwarp();

        // ---- warp-cooperative coalesced output flush ----
        {
            const size_t row = (size_t)t * B + wb;
            const float4* s4 = (const float4*)stg;
            float4* d0 = (float4*)(p_ssh + row * 28);       // 224 float4
#pragma unroll
            for (int k = 0; k < 7; k++)
                __stcs(d0 + lane + 32 * k, s4[OSH / 4 + lane + 32 * k]);
            float4* d1 = (float4*)(p_sch + row * 8);        // 64
#pragma unroll
            for (int k = 0; k < 2; k++)
                __stcs(d1 + lane + 32 * k, s4[OSCH / 4 + lane + 32 * k]);
            float4* d2 = (float4*)(p_srh + row * 14);       // 112
#pragma unroll
            for (int k = 0; k < 4; k++) {
                int i = lane + 32 * k;
                if (i < 112) __stcs(d2 + i, s4[OSRH / 4 + i]);
            }
            float4* d3 = (float4*)(p_mco + row * 3);        // 24
            if (lane < 24) __stcs(d3 + lane, s4[OMCO / 4 + lane]);
            float4* d4 = (float4*)(p_mro + row);            // 8
            if (lane < 8) __stcs(d4 + lane, s4[OMRO / 4 + lane]);
        }
        __syncwarp();   // flush reads done before next step's x load overwrites
    }
}

extern "C" void kernel_launch(void* const* d_in, const int* in_sizes, int n_in,
                              void* d_out, int out_size) {
    const float* x   = (const float*)d_in[0];
    const float* Wsh = (const float*)d_in[1];
    const float* bsh = (const float*)d_in[2];
    const float* Wch = (const float*)d_in[3];
    const float* bch = (const float*)d_in[4];
    const float* Wco = (const float*)d_in[5];
    const float* bco = (const float*)d_in[6];
    const float* Wrh = (const float*)d_in[7];
    const float* brh = (const float*)d_in[8];
    const float* Wro = (const float*)d_in[9];
    const float* bro = (const float*)d_in[10];

    const int B = in_sizes[0] / (TT * NIN);
    const int blocks = (B + THREADS - 1) / THREADS;

    cudaFuncSetAttribute(snn_kernel,
                         cudaFuncAttributeMaxDynamicSharedMemorySize, SMEM_BYTES);

    snn_kernel<<<blocks, THREADS, SMEM_BYTES>>>(x, Wsh, bsh, Wch, bch, Wco, bco,
                                                Wrh, brh, Wro, bro,
                                                (float*)d_out, B);
}